// round 16
// baseline (speedup 1.0000x reference)
#include <cuda_runtime.h>

#define RES    16
#define HID    32
#define CONDN  10
#define NOUT   256
#define BLOCK  256
#define WARPS  8
#define TP     16      // samples per warp-pair per iteration
#define PAIRS  4       // sample-pairs per warp in layers 0-2 (8 samples)
#define FULLM  0xffffffffu
#define EPSF   1e-12f
#define HROW   20
#define HIST_STRIDE (RES*HROW)   // 320

// ---- shared layout (float offsets) ----
#define OFF_W0    0                    // 320
#define OFF_W1    (OFF_W0 + 320)      // 1024
#define OFF_W2    (OFF_W1 + 1024)     // 1024
#define OFF_W3Q   (OFF_W2 + 1024)     // 8192 floats, float4-packed k-pairs (16B aligned: 2368*4=9472)
#define OFF_PAIR  (OFF_W3Q + 8192)    // 10560
#define PAIR_COND 0                    // 2 warps x 80 f
#define PAIR_HIST 160                  // 8 slots x 320 = 2560 f ; smh aliases first 512 f
#define PAIR_SIZE_F (PAIR_HIST + 8*HIST_STRIDE)       // 2720
#define SMEM_FLOATS (OFF_PAIR + 4*PAIR_SIZE_F)        // 21440
#define SMEM_BYTES  (SMEM_FLOATS*4)                   // 85760 B -> 2 CTAs/SM

// packed fp32x2 FMA (sm_100+): FFMA2 in SASS
__device__ __forceinline__ float2 ffma2(float2 a, float2 b, float2 c) {
    float2 d;
    asm("fma.rn.f32x2 %0, %1, %2, %3;"
        : "=l"(reinterpret_cast<unsigned long long&>(d))
        : "l"(reinterpret_cast<unsigned long long&>(a)),
          "l"(reinterpret_cast<unsigned long long&>(b)),
          "l"(reinterpret_cast<unsigned long long&>(c)));
    return d;
}
__device__ __forceinline__ float2 dup2(float v) { return make_float2(v, v); }

__device__ __forceinline__ float softplusf(float z) {
    float a = fabsf(z);
    float e = __expf(-a);
    float l = __logf(1.0f + e);
    return fmaxf(z, 0.0f) + l;
}

// inclusive scan within 16-lane halves
__device__ __forceinline__ float scan16(float v, int yl) {
    #pragma unroll
    for (int off = 1; off < 16; off <<= 1) {
        float u = __shfl_up_sync(FULLM, v, off);
        if (yl >= off) v += u;
    }
    return v;
}

__global__ __launch_bounds__(BLOCK, 2)
void hist2d_inv_kernel(
    const float* __restrict__ wi,  const float* __restrict__ cond,
    const float* __restrict__ w0,  const float* __restrict__ b0,
    const float* __restrict__ w1,  const float* __restrict__ b1,
    const float* __restrict__ w2,  const float* __restrict__ b2,
    const float* __restrict__ w3,  const float* __restrict__ b3,
    float* __restrict__ out, int B)
{
    extern __shared__ float sm[];
    const int tid = threadIdx.x;

    // ---- cooperative weight staging ----
    for (int i = tid; i < CONDN*HID; i += BLOCK) sm[OFF_W0 + i] = w0[i];
    for (int i = tid; i < HID*HID; i += BLOCK) {
        sm[OFF_W1 + i] = w1[i]; sm[OFF_W2 + i] = w2[i];
    }
    // w3 packed as float4 per (k-pair, P, j): (w3[k][m0], w3[k][m0+32], w3[k+1][m0], w3[k+1][m0+32])
    // where m0 = P*64 + j.  float2 store index: ((k>>1)*128 + P*32 + j)*2 + (k&1)
    {
        float2* w3q2 = (float2*)(sm + OFF_W3Q);
        for (int i = tid; i < HID*128; i += BLOCK) {
            int k = i >> 7, r = i & 127, P = r >> 5, j = r & 31;
            w3q2[(((k >> 1)*128 + P*32 + j) << 1) + (k & 1)] =
                make_float2(w3[k*NOUT + P*64 + j], w3[k*NOUT + P*64 + 32 + j]);
        }
    }
    __syncthreads();

    const int lane = tid & 31;
    const int warp = tid >> 5;
    const int wp   = warp & 1;          // warp-in-pair
    const int pr_id = warp >> 1;        // pair index within CTA (0..3)
    const int bar_id = 1 + pr_id;       // named barrier id (0 reserved for __syncthreads)

    float*  pbase = sm + OFF_PAIR + pr_id * PAIR_SIZE_F;
    float2* smc2  = (float2*)(pbase + PAIR_COND + wp*80);            // [pair][10] per warp
    float2* smh2w = (float2*)(pbase + PAIR_HIST + wp*256);           // own h region (aliases hist slots 0-1)
    const float4* hsm4 = (const float4*)(pbase + PAIR_HIST);          // both warps' h, float4 view
    const float4* w3q4 = (const float4*)(sm + OFF_W3Q);
    float*  hist  = pbase + PAIR_HIST;                                // [8][320]

    // ---- lane-invariant biases in registers ----
    const float2 bb0 = dup2(b0[lane]);
    const float2 bb1 = dup2(b1[lane]);
    const float2 bb2 = dup2(b2[lane]);
    float2 b3r[2];
    #pragma unroll
    for (int p = 0; p < 2; p++) {
        int m0 = wp*128 + p*64 + lane;
        b3r[p] = make_float2(b3[m0], b3[m0 + 32]);
    }

    const int gpair  = blockIdx.x * (WARPS/2) + pr_id;
    const int npairs = gridDim.x * (WARPS/2);
    const int half = lane >> 4;
    const int yl   = lane & 15;
    const int base = half << 4;

    for (int s0 = gpair * TP; s0 < B; s0 += npairs * TP) {
        const int sW = s0 + wp*8;   // this warp's 8 samples for layers 0-2

        // ---- stage cond pairs into own region ----
        #pragma unroll
        for (int idx = lane; idx < 8*CONDN; idx += 32) {
            int t = idx / CONDN, i = idx - t*CONDN;
            int s = min(sW + t, B - 1);
            ((float*)smc2)[((t >> 1)*CONDN + i)*2 + (t & 1)] = cond[s*CONDN + i];
        }
        __syncwarp();

        // ---- layer 0: 10 -> 32 ----
        {
            float2 acc[PAIRS];
            #pragma unroll
            for (int pr = 0; pr < PAIRS; pr++) acc[pr] = bb0;
            #pragma unroll
            for (int i = 0; i < CONDN; i++) {
                float2 wd = dup2(sm[OFF_W0 + i*HID + lane]);
                #pragma unroll
                for (int pr = 0; pr < PAIRS; pr++)
                    acc[pr] = ffma2(smc2[pr*CONDN + i], wd, acc[pr]);
            }
            __syncwarp();
            #pragma unroll
            for (int pr = 0; pr < PAIRS; pr++)
                smh2w[pr*HID + lane] = make_float2(fmaxf(acc[pr].x, 0.0f), fmaxf(acc[pr].y, 0.0f));
            __syncwarp();
        }

        // ---- layers 1,2: 32 -> 32 ----
        #pragma unroll
        for (int L = 0; L < 2; L++) {
            const float* W = sm + (L == 0 ? OFF_W1 : OFF_W2);
            float2 acc[PAIRS];
            float2 bbL = (L == 0) ? bb1 : bb2;
            #pragma unroll
            for (int pr = 0; pr < PAIRS; pr++) acc[pr] = bbL;
            #pragma unroll
            for (int k = 0; k < HID; k += 2) {
                float2 wd0 = dup2(W[k*HID + lane]);
                float2 wd1 = dup2(W[(k+1)*HID + lane]);
                #pragma unroll
                for (int pr = 0; pr < PAIRS; pr++) {
                    float4 hq = ((const float4*)smh2w)[pr*16 + (k >> 1)];
                    acc[pr] = ffma2(make_float2(hq.x, hq.y), wd0, acc[pr]);
                    acc[pr] = ffma2(make_float2(hq.z, hq.w), wd1, acc[pr]);
                }
            }
            __syncwarp();
            #pragma unroll
            for (int pr = 0; pr < PAIRS; pr++)
                smh2w[pr*HID + lane] = make_float2(fmaxf(acc[pr].x, 0.0f), fmaxf(acc[pr].y, 0.0f));
            __syncwarp();
        }

        // ---- pair barrier A: both warps' h visible ----
        asm volatile("bar.sync %0, 64;" :: "r"(bar_id) : "memory");

        // ---- layer 3: this warp computes m in [wp*128, wp*128+128) for ALL 16 samples ----
        float2 acc3[TP][2];
        #pragma unroll
        for (int p = 0; p < 2; p++) {
            #pragma unroll
            for (int t = 0; t < TP; t++) acc3[t][p] = b3r[p];
        }
        #pragma unroll 4
        for (int kh = 0; kh < 16; kh++) {        // k-pair index: k = 2*kh, 2*kh+1
            float4 q0 = w3q4[kh*128 + (wp*2 + 0)*32 + lane];
            float4 q1 = w3q4[kh*128 + (wp*2 + 1)*32 + lane];
            float2 wv00 = make_float2(q0.x, q0.y), wv01 = make_float2(q0.z, q0.w);
            float2 wv10 = make_float2(q1.x, q1.y), wv11 = make_float2(q1.z, q1.w);
            #pragma unroll
            for (int sp = 0; sp < 8; sp++) {     // sample-pair: samples 2sp, 2sp+1
                float4 hq = hsm4[(sp >> 2)*64 + (sp & 3)*16 + kh];
                float2 ha = make_float2(hq.x, hq.x);   // h[2sp][2kh]
                float2 hb = make_float2(hq.y, hq.y);   // h[2sp+1][2kh]
                float2 hc = make_float2(hq.z, hq.z);   // h[2sp][2kh+1]
                float2 hd = make_float2(hq.w, hq.w);   // h[2sp+1][2kh+1]
                int t0 = 2*sp, t1 = 2*sp + 1;
                acc3[t0][0] = ffma2(wv00, ha, acc3[t0][0]);
                acc3[t1][0] = ffma2(wv00, hb, acc3[t1][0]);
                acc3[t0][0] = ffma2(wv01, hc, acc3[t0][0]);
                acc3[t1][0] = ffma2(wv01, hd, acc3[t1][0]);
                acc3[t0][1] = ffma2(wv10, ha, acc3[t0][1]);
                acc3[t1][1] = ffma2(wv10, hb, acc3[t1][1]);
                acc3[t0][1] = ffma2(wv11, hc, acc3[t0][1]);
                acc3[t1][1] = ffma2(wv11, hd, acc3[t1][1]);
            }
        }

        // ---- pair barrier B: layer-3 h reads done before staging overwrites aliased slots ----
        asm volatile("bar.sync %0, 64;" :: "r"(bar_id) : "memory");

        // ---- two phases: stage 8 histograms (row-halves from each warp), sample 4 per warp ----
        #pragma unroll
        for (int ph = 0; ph < 2; ph++) {
            #pragma unroll
            for (int tt = 0; tt < 8; tt++) {
                int t = ph*8 + tt;
                float* Ht = hist + tt * HIST_STRIDE;
                #pragma unroll
                for (int p = 0; p < 2; p++) {
                    float v0 = softplusf(acc3[t][p].x);   // m0 = wp*128 + p*64 + lane
                    float v1 = softplusf(acc3[t][p].y);   // m1 = m0 + 32
                    int m0 = wp*128 + p*64 + lane;
                    Ht[(m0 >> 4)*HROW + (m0 & 15)] = v0;
                    int m1 = m0 + 32;
                    Ht[(m1 >> 4)*HROW + (m1 & 15)] = v1;
                }
            }
            // pair barrier: all 8 slots fully staged
            asm volatile("bar.sync %0, 64;" :: "r"(bar_id) : "memory");

            // each warp samples 4 slots: wp*4 + it*2 + half
            #pragma unroll
            for (int it = 0; it < 2; it++) {
                int slot = wp*4 + it*2 + half;
                int s = s0 + ph*8 + slot;
                bool valid = (s < B);
                int sc = min(s, B - 1);
                float2 uu = *(const float2*)(wi + 2*sc);
                float ux = uu.x, uy = uu.y;
                const float* Ht = hist + slot * HIST_STRIDE;

                const float4* r4 = (const float4*)(Ht + yl*HROW);
                float4 a = r4[0], bq = r4[1], cq = r4[2], dq = r4[3];
                float rs = ((a.x + a.y) + (a.z + a.w)) + ((bq.x + bq.y) + (bq.z + bq.w))
                         + ((cq.x + cq.y) + (cq.z + cq.w)) + ((dq.x + dq.y) + (dq.z + dq.w));

                float C = scan16(rs, yl);                         // unnormalized cdf_y
                float S = __shfl_sync(FULLM, C, base + 15);
                float Sm = fmaxf(S, EPSF);
                float invS = 1.0f / Sm;
                float ty = uy * Sm;                               // C < uy*S <=> cdf_y < uy
                unsigned my = (__ballot_sync(FULLM, C < ty) >> base) & 0xFFFFu;
                int iy = __popc(my); if (iy > 15) iy = 15;
                float Cprev = __shfl_sync(FULLM, C, base + ((iy > 0) ? (iy - 1) : 0));
                if (iy == 0) Cprev = 0.0f;
                float py = __shfl_sync(FULLM, rs, base + iy);
                float yout = ((float)iy + (uy - Cprev*invS) / fmaxf(py*invS, EPSF)) * (1.0f/RES);

                float vr = Ht[iy*HROW + yl];
                float D = scan16(vr, yl);
                float tx = ux * py;                               // D < ux*py <=> cdf_x < ux
                unsigned mx = (__ballot_sync(FULLM, D < tx) >> base) & 0xFFFFu;
                int ix = __popc(mx); if (ix > 15) ix = 15;
                float Dprev = __shfl_sync(FULLM, D, base + ((ix > 0) ? (ix - 1) : 0));
                if (ix == 0) Dprev = 0.0f;
                float px = __shfl_sync(FULLM, vr, base + ix);
                float invpy = 1.0f / py;
                float xout = ((float)ix + (ux - Dprev*invpy) / fmaxf(px*invpy, EPSF)) * (1.0f/RES);
                float pdf = px * invS * ((float)(RES*RES) * 0.25f);

                if (valid && yl == 0) {
                    *(float2*)(out + 2*s) = make_float2(xout*2.0f - 1.0f, yout*2.0f - 1.0f);
                    out[2*B + s] = pdf;
                }
            }
            // pair barrier: sampling reads done before next phase / next iteration overwrites
            asm volatile("bar.sync %0, 64;" :: "r"(bar_id) : "memory");
        }
    }
}

extern "C" void kernel_launch(void* const* d_in, const int* in_sizes, int n_in,
                              void* d_out, int out_size)
{
    const float* wi   = (const float*)d_in[0];
    const float* cond = (const float*)d_in[1];
    const float* w0   = (const float*)d_in[2];
    const float* b0   = (const float*)d_in[3];
    const float* w1   = (const float*)d_in[4];
    const float* b1   = (const float*)d_in[5];
    const float* w2   = (const float*)d_in[6];
    const float* b2   = (const float*)d_in[7];
    const float* w3   = (const float*)d_in[8];
    const float* b3   = (const float*)d_in[9];

    int B = in_sizes[0] / 2;

    cudaFuncSetAttribute(hist2d_inv_kernel,
                         cudaFuncAttributeMaxDynamicSharedMemorySize, SMEM_BYTES);

    // 2 CTAs/SM x 256 threads = 16 warps/SM on 152-SM GB300
    hist2d_inv_kernel<<<304, BLOCK, SMEM_BYTES>>>(
        wi, cond, w0, b0, w1, b1, w2, b2, w3, b3, (float*)d_out, B);
}